// round 8
// baseline (speedup 1.0000x reference)
#include <cuda_runtime.h>
#include <cuda_fp16.h>

#define NN   100000
#define EE   3200000
#define DIN  16
#define DOUT 32
#define CAP  128
#define NPW  8        // nodes per warp in k_gather

// Static device scratch.
__device__ __align__(32) __half g_hh[NN * DIN];   // 3.2 MB fp16 — h (both paths)
__device__ __align__(16) int g_cnt[NN];           // per-dst in-degree
__device__ int g_bucket[NN * CAP];                // padded CSR of src indices

// ---------------------------------------------------------------------------
// Kernel 0: zero the per-destination counters.
// ---------------------------------------------------------------------------
__global__ void k_zero(int n4)
{
    int i = blockIdx.x * blockDim.x + threadIdx.x;
    if (i < n4) reinterpret_cast<int4*>(g_cnt)[i] = make_int4(0, 0, 0, 0);
}

// ---------------------------------------------------------------------------
// Kernel 1: scatter edges into padded per-destination buckets, 8 edges/thread.
// ---------------------------------------------------------------------------
__global__ void k_scatter(const int* __restrict__ edge, int e8, int e)
{
    int i = blockIdx.x * blockDim.x + threadIdx.x;
    if (i >= e8) return;
    const int4* srcp = reinterpret_cast<const int4*>(edge);
    const int4* dstp = reinterpret_cast<const int4*>(edge + e);
    int4 sa = srcp[2 * i], sb = srcp[2 * i + 1];
    int4 da = dstp[2 * i], db = dstp[2 * i + 1];
    const int sv[8] = {sa.x, sa.y, sa.z, sa.w, sb.x, sb.y, sb.z, sb.w};
    const int dv[8] = {da.x, da.y, da.z, da.w, db.x, db.y, db.z, db.w};

    int pos[8];
    #pragma unroll
    for (int q = 0; q < 8; q++) pos[q] = atomicAdd(&g_cnt[dv[q]], 1);
    #pragma unroll
    for (int q = 0; q < 8; q++)
        if (pos[q] < CAP) g_bucket[(size_t)dv[q] * CAP + pos[q]] = sv[q];
}

// ---------------------------------------------------------------------------
// Kernel 2: fused MLP  h = relu(x@w1+b1)@w2 + b2; 2 threads/node, fp16 out.
// ---------------------------------------------------------------------------
__global__ void k_mlp(const float* __restrict__ x,
                      const float* __restrict__ w1, const float* __restrict__ b1,
                      const float* __restrict__ w2, const float* __restrict__ b2,
                      int n)
{
    __shared__ float sw1[DIN * DIN], sw2[DIN * DIN], sb1[DIN], sb2[DIN];
    int t = threadIdx.x;
    if (t < DIN * DIN) { sw1[t] = w1[t]; sw2[t] = w2[t]; }
    if (t < DIN)       { sb1[t] = b1[t]; sb2[t] = b2[t]; }
    __syncthreads();

    int gid  = blockIdx.x * blockDim.x + t;
    int i    = gid >> 1;
    int half = gid & 1;
    if (i >= n) return;

    float xv[DIN];
    const float4* xp = reinterpret_cast<const float4*>(x + (size_t)i * DIN);
    #pragma unroll
    for (int q = 0; q < 4; q++) {
        float4 v = xp[q];
        xv[q * 4 + 0] = v.x; xv[q * 4 + 1] = v.y;
        xv[q * 4 + 2] = v.z; xv[q * 4 + 3] = v.w;
    }

    float tv[DIN];
    #pragma unroll
    for (int j = 0; j < DIN; j++) {
        float s = sb1[j];
        #pragma unroll
        for (int k = 0; k < DIN; k++) s = fmaf(xv[k], sw1[k * DIN + j], s);
        tv[j] = fmaxf(s, 0.0f);
    }

    const int jb = half * 8;
    float hv[8];
    #pragma unroll
    for (int j = 0; j < 8; j++) {
        float s = sb2[jb + j];
        #pragma unroll
        for (int k = 0; k < DIN; k++) s = fmaf(tv[k], sw2[k * DIN + jb + j], s);
        hv[j] = s;
    }

    __half2 hh[4];
    #pragma unroll
    for (int q = 0; q < 4; q++)
        hh[q] = __floats2half2_rn(hv[2 * q], hv[2 * q + 1]);
    *reinterpret_cast<uint4*>(g_hh + (size_t)i * DIN + jb) =
        *reinterpret_cast<uint4*>(&hh[0]);
}

// ---------------------------------------------------------------------------
// Kernel 3: gather. 4 lanes per neighbor (LDG.64 each), weights in registers
// amortized over NPW nodes per warp, zero shared-memory epilogue.
// Lane covers dims [4*(lane&3), +4); slot group = lane>>2 (8 slots/pass).
// ---------------------------------------------------------------------------
__global__ void k_gather(const float* __restrict__ wl, const float* __restrict__ bl,
                         const float* __restrict__ wr, float* __restrict__ out, int n)
{
    const int lane = threadIdx.x & 31;
    const int gw   = (blockIdx.x * blockDim.x + threadIdx.x) >> 5;

    // per-lane output-column weights (coalesced, amortized over NPW nodes)
    float rwl[DIN], rwr[DIN];
    #pragma unroll
    for (int k = 0; k < DIN; k++) rwl[k] = wl[k * DOUT + lane];
    #pragma unroll
    for (int k = 0; k < DIN; k++) rwr[k] = wr[k * DOUT + lane];
    const float rbl = bl[lane];

    const int slot = lane >> 2;   // 0..7
    const int qsel = lane & 3;    // which 8 B of the 32 B row

    int node0 = gw * NPW;
    #pragma unroll 1
    for (int t = 0; t < NPW; t++) {
        int nd = node0 + t;
        if (nd >= n) return;

        int cnt = g_cnt[nd];
        int m   = min(cnt, CAP);
        const int* bk = g_bucket + (size_t)nd * CAP;

        float a0 = 0.f, a1 = 0.f, a2 = 0.f, a3 = 0.f;
        const uint2 z2 = make_uint2(0u, 0u);

        for (int base = 0; base < m; base += 64) {
            uint2 u[8];
            #pragma unroll
            for (int j = 0; j < 8; j++) {
                int  idx = base + slot + 8 * j;
                bool ok  = idx < m;
                int  s   = ok ? bk[idx] : 0;
                u[j] = ok ? *(reinterpret_cast<const uint2*>(g_hh + (size_t)s * DIN) + qsel)
                          : z2;
            }
            #pragma unroll
            for (int jp = 0; jp < 4; jp++) {
                __half2 p0 = __hadd2(*reinterpret_cast<const __half2*>(&u[2 * jp].x),
                                     *reinterpret_cast<const __half2*>(&u[2 * jp + 1].x));
                __half2 p1 = __hadd2(*reinterpret_cast<const __half2*>(&u[2 * jp].y),
                                     *reinterpret_cast<const __half2*>(&u[2 * jp + 1].y));
                float2 f0 = __half22float2(p0);
                float2 f1 = __half22float2(p1);
                a0 += f0.x; a1 += f0.y; a2 += f1.x; a3 += f1.y;
            }
        }

        // reduce across the 8 slot-groups (lanes sharing the same qsel)
        #pragma unroll
        for (int off = 4; off < 32; off <<= 1) {
            a0 += __shfl_xor_sync(0xffffffffu, a0, off);
            a1 += __shfl_xor_sync(0xffffffffu, a1, off);
            a2 += __shfl_xor_sync(0xffffffffu, a2, off);
            a3 += __shfl_xor_sync(0xffffffffu, a3, off);
        }

        float inv = 1.0f / (float)max(cnt, 1);
        a0 *= inv; a1 *= inv; a2 *= inv; a3 *= inv;

        // broadcast full 16-dim mean to every lane (quarter q lives in lane q)
        float mean[DIN];
        #pragma unroll
        for (int q = 0; q < 4; q++) {
            mean[4 * q + 0] = __shfl_sync(0xffffffffu, a0, q);
            mean[4 * q + 1] = __shfl_sync(0xffffffffu, a1, q);
            mean[4 * q + 2] = __shfl_sync(0xffffffffu, a2, q);
            mean[4 * q + 3] = __shfl_sync(0xffffffffu, a3, q);
        }

        float v = rbl;
        #pragma unroll
        for (int k = 0; k < DIN; k++) v = fmaf(mean[k], rwl[k], v);

        // root features: full 32 B fp16 row = TWO uint4 loads (16 halves)
        const uint4* rptr = reinterpret_cast<const uint4*>(g_hh + (size_t)nd * DIN);
        uint4 ur0 = rptr[0];
        uint4 ur1 = rptr[1];
        const __half2* rp0 = reinterpret_cast<const __half2*>(&ur0);
        const __half2* rp1 = reinterpret_cast<const __half2*>(&ur1);
        #pragma unroll
        for (int q = 0; q < 4; q++) {
            float2 f = __half22float2(rp0[q]);
            v = fmaf(f.x, rwr[2 * q],     v);
            v = fmaf(f.y, rwr[2 * q + 1], v);
        }
        #pragma unroll
        for (int q = 0; q < 4; q++) {
            float2 f = __half22float2(rp1[q]);
            v = fmaf(f.x, rwr[8 + 2 * q],     v);
            v = fmaf(f.y, rwr[8 + 2 * q + 1], v);
        }
        out[(size_t)nd * DOUT + lane] = v;
    }
}

// ---------------------------------------------------------------------------
// Order: zero -> scatter -> mlp -> gather (4-launch period keeps ncu on gather).
// ---------------------------------------------------------------------------
extern "C" void kernel_launch(void* const* d_in, const int* in_sizes, int n_in,
                              void* d_out, int out_size)
{
    const float* x    = (const float*)d_in[0];
    const int*   edge = (const int*)d_in[1];
    const float* w1   = (const float*)d_in[2];
    const float* b1   = (const float*)d_in[3];
    const float* w2   = (const float*)d_in[4];
    const float* b2   = (const float*)d_in[5];
    const float* wl   = (const float*)d_in[6];
    const float* bl   = (const float*)d_in[7];
    const float* wr   = (const float*)d_in[8];
    float*       out  = (float*)d_out;

    int n  = in_sizes[0] / DIN;   // 100000
    int e  = in_sizes[1] / 2;     // 3200000
    int e8 = e / 8;
    int n4 = (n + 3) / 4;

    k_zero<<<(n4 + 255) / 256, 256>>>(n4);
    k_scatter<<<(e8 + 255) / 256, 256>>>(edge, e8, e);
    k_mlp<<<((size_t)n * 2 + 255) / 256, 256>>>(x, w1, b1, w2, b2, n);

    int warps = (n + NPW - 1) / NPW;
    k_gather<<<(warps * 32 + 255) / 256, 256>>>(wl, bl, wr, out, n);
}

// round 10
// speedup vs baseline: 1.2501x; 1.2501x over previous
#include <cuda_runtime.h>
#include <cuda_fp16.h>

#define NN   100000
#define EE   3200000
#define DIN  16
#define DOUT 32
#define CAP  128
#define NPW  4        // nodes per warp in k_gather

// Static device scratch.
__device__ __align__(32) __half g_hh[NN * DIN];    // 3.2 MB fp16 — neighbor-path h
__device__ __align__(16) float  g_r [NN * DOUT];   // 12.8 MB fp32 — h@wr + bl
__device__ __align__(16) int g_cnt[NN];            // per-dst in-degree
__device__ int g_bucket[NN * CAP];                 // padded CSR of src indices

// ---------------------------------------------------------------------------
// Kernel 0: zero the per-destination counters.
// ---------------------------------------------------------------------------
__global__ void k_zero(int n4)
{
    int i = blockIdx.x * blockDim.x + threadIdx.x;
    if (i < n4) reinterpret_cast<int4*>(g_cnt)[i] = make_int4(0, 0, 0, 0);
}

// ---------------------------------------------------------------------------
// Kernel 1: scatter edges into padded per-destination buckets, 8 edges/thread.
// ---------------------------------------------------------------------------
__global__ void k_scatter(const int* __restrict__ edge, int e8, int e)
{
    int i = blockIdx.x * blockDim.x + threadIdx.x;
    if (i >= e8) return;
    const int4* srcp = reinterpret_cast<const int4*>(edge);
    const int4* dstp = reinterpret_cast<const int4*>(edge + e);
    int4 sa = srcp[2 * i], sb = srcp[2 * i + 1];
    int4 da = dstp[2 * i], db = dstp[2 * i + 1];
    const int sv[8] = {sa.x, sa.y, sa.z, sa.w, sb.x, sb.y, sb.z, sb.w};
    const int dv[8] = {da.x, da.y, da.z, da.w, db.x, db.y, db.z, db.w};

    int pos[8];
    #pragma unroll
    for (int q = 0; q < 8; q++) pos[q] = atomicAdd(&g_cnt[dv[q]], 1);
    #pragma unroll
    for (int q = 0; q < 8; q++)
        if (pos[q] < CAP) g_bucket[(size_t)dv[q] * CAP + pos[q]] = sv[q];
}

// ---------------------------------------------------------------------------
// Kernel 2: fused MLP. 2 threads/node. Each thread computes 8 of 16 h dims,
// stores fp16 half-row, and the pair cooperatively computes
// g_r = h @ wr + bl (fp32, full 32 dims) via one shfl_xor(1) combine.
// ---------------------------------------------------------------------------
__global__ void k_mlp(const float* __restrict__ x,
                      const float* __restrict__ w1, const float* __restrict__ b1,
                      const float* __restrict__ w2, const float* __restrict__ b2,
                      const float* __restrict__ wr, const float* __restrict__ bl,
                      int n)
{
    __shared__ float sw1[DIN * DIN], sw2[DIN * DIN], sb1[DIN], sb2[DIN];
    __shared__ float swr[DIN * DOUT], sbl[DOUT];
    int t = threadIdx.x;
    if (t < DIN * DIN) { sw1[t] = w1[t]; sw2[t] = w2[t]; }
    if (t < DIN)       { sb1[t] = b1[t]; sb2[t] = b2[t]; }
    swr[t] = wr[t]; swr[t + 256] = wr[t + 256];
    if (t < DOUT) sbl[t] = bl[t];
    __syncthreads();

    int gid  = blockIdx.x * blockDim.x + t;
    int i    = gid >> 1;
    int half = gid & 1;          // == t & 1, partner is adjacent lane
    if (i >= n) return;

    float xv[DIN];
    const float4* xp = reinterpret_cast<const float4*>(x + (size_t)i * DIN);
    #pragma unroll
    for (int q = 0; q < 4; q++) {
        float4 v = xp[q];
        xv[q * 4 + 0] = v.x; xv[q * 4 + 1] = v.y;
        xv[q * 4 + 2] = v.z; xv[q * 4 + 3] = v.w;
    }

    float tv[DIN];
    #pragma unroll
    for (int j = 0; j < DIN; j++) {
        float s = sb1[j];
        #pragma unroll
        for (int k = 0; k < DIN; k++) s = fmaf(xv[k], sw1[k * DIN + j], s);
        tv[j] = fmaxf(s, 0.0f);
    }

    const int jb = half * 8;
    float hv[8];
    #pragma unroll
    for (int j = 0; j < 8; j++) {
        float s = sb2[jb + j];
        #pragma unroll
        for (int k = 0; k < DIN; k++) s = fmaf(tv[k], sw2[k * DIN + jb + j], s);
        hv[j] = s;
    }

    // fp16 half-row for the gather path
    __half2 hh[4];
    #pragma unroll
    for (int q = 0; q < 4; q++)
        hh[q] = __floats2half2_rn(hv[2 * q], hv[2 * q + 1]);
    *reinterpret_cast<uint4*>(g_hh + (size_t)i * DIN + jb) =
        *reinterpret_cast<uint4*>(&hh[0]);

    // r = h @ wr + bl : partial over this thread's 8 h dims, all 32 columns
    float pr[DOUT];
    #pragma unroll
    for (int c = 0; c < DOUT; c++) pr[c] = 0.0f;
    #pragma unroll
    for (int k = 0; k < 8; k++) {
        float hk = hv[k];
        #pragma unroll
        for (int c = 0; c < DOUT; c++)
            pr[c] = fmaf(hk, swr[(jb + k) * DOUT + c], pr[c]);
    }
    #pragma unroll
    for (int c = 0; c < DOUT; c++)
        pr[c] += __shfl_xor_sync(0xffffffffu, pr[c], 1);

    // this thread writes columns [half*16, half*16+16)
    const int cb = half * 16;
    float4* rp = reinterpret_cast<float4*>(g_r + (size_t)i * DOUT + cb);
    #pragma unroll
    for (int q = 0; q < 4; q++)
        rp[q] = make_float4(pr[cb + 4 * q + 0] + sbl[cb + 4 * q + 0],
                            pr[cb + 4 * q + 1] + sbl[cb + 4 * q + 1],
                            pr[cb + 4 * q + 2] + sbl[cb + 4 * q + 2],
                            pr[cb + 4 * q + 3] + sbl[cb + 4 * q + 3]);
}

// ---------------------------------------------------------------------------
// Kernel 3: gather. Quartet scheme: lane's q = lane&3 owns dims [4q,4q+4),
// slot = lane>>2 walks 8 neighbors/pass (2-wide unrolled -> 16/iter).
// Slot-reduce = 12 shfl; GEMV via column-xor trick = 16 FMA + 3 shfl,
// weights fixed per lane in 16 registers. Root term read from g_r.
// ---------------------------------------------------------------------------
__global__ void k_gather(const float* __restrict__ wl, float* __restrict__ out, int n)
{
    const int lane = threadIdx.x & 31;
    const int gw   = (blockIdx.x * blockDim.x + threadIdx.x) >> 5;
    const int q    = lane & 3;
    const int slot = lane >> 2;

    // rwl[d*4+j] = wl[(4q+j)][lane^d] — fixed per lane, amortized over NPW nodes
    float rwl[16];
    #pragma unroll
    for (int d = 0; d < 4; d++)
        #pragma unroll
        for (int j = 0; j < 4; j++)
            rwl[d * 4 + j] = wl[(4 * q + j) * DOUT + (lane ^ d)];

    const int node0 = gw * NPW;
    #pragma unroll 1
    for (int t = 0; t < NPW; t++) {
        int nd = node0 + t;
        if (nd >= n) return;

        int cnt = g_cnt[nd];
        int m   = min(cnt, CAP);
        const int* bk = g_bucket + (size_t)nd * CAP;

        float a0 = 0.f, a1 = 0.f, a2 = 0.f, a3 = 0.f;
        const uint2 z2 = make_uint2(0u, 0u);

        for (int base = 0; base < m; base += 16) {
            int  i0 = base + slot, i1 = i0 + 8;
            bool k0 = i0 < m,      k1 = i1 < m;
            int  s0 = k0 ? bk[i0] : 0;
            int  s1 = k1 ? bk[i1] : 0;
            uint2 u0 = k0 ? *reinterpret_cast<const uint2*>(g_hh + (size_t)s0 * DIN + 4 * q) : z2;
            uint2 u1 = k1 ? *reinterpret_cast<const uint2*>(g_hh + (size_t)s1 * DIN + 4 * q) : z2;

            float2 f0 = __half22float2(*reinterpret_cast<__half2*>(&u0.x));
            float2 f1 = __half22float2(*reinterpret_cast<__half2*>(&u0.y));
            float2 f2 = __half22float2(*reinterpret_cast<__half2*>(&u1.x));
            float2 f3 = __half22float2(*reinterpret_cast<__half2*>(&u1.y));
            a0 += f0.x + f2.x; a1 += f0.y + f2.y;
            a2 += f1.x + f3.x; a3 += f1.y + f3.y;
        }

        // reduce across the 8 slot groups (lane bits 2,3,4)
        #pragma unroll
        for (int off = 4; off < 32; off <<= 1) {
            a0 += __shfl_xor_sync(0xffffffffu, a0, off);
            a1 += __shfl_xor_sync(0xffffffffu, a1, off);
            a2 += __shfl_xor_sync(0xffffffffu, a2, off);
            a3 += __shfl_xor_sync(0xffffffffu, a3, off);
        }

        float inv = 1.0f / (float)max(cnt, 1);
        a0 *= inv; a1 *= inv; a2 *= inv; a3 *= inv;

        // p_d = partial of out column (lane^d) over this quartet's 4 dims
        float p0 = fmaf(a0, rwl[0],  fmaf(a1, rwl[1],  fmaf(a2, rwl[2],  a3 * rwl[3])));
        float p1 = fmaf(a0, rwl[4],  fmaf(a1, rwl[5],  fmaf(a2, rwl[6],  a3 * rwl[7])));
        float p2 = fmaf(a0, rwl[8],  fmaf(a1, rwl[9],  fmaf(a2, rwl[10], a3 * rwl[11])));
        float p3 = fmaf(a0, rwl[12], fmaf(a1, rwl[13], fmaf(a2, rwl[14], a3 * rwl[15])));

        float A = p0 + __shfl_xor_sync(0xffffffffu, p1, 1);
        float B = p2 + __shfl_xor_sync(0xffffffffu, p3, 1);
        float v = A + __shfl_xor_sync(0xffffffffu, B, 2);

        v += g_r[(size_t)nd * DOUT + lane];
        out[(size_t)nd * DOUT + lane] = v;
    }
}

// ---------------------------------------------------------------------------
// Order: zero -> scatter -> mlp -> gather.
// ---------------------------------------------------------------------------
extern "C" void kernel_launch(void* const* d_in, const int* in_sizes, int n_in,
                              void* d_out, int out_size)
{
    const float* x    = (const float*)d_in[0];
    const int*   edge = (const int*)d_in[1];
    const float* w1   = (const float*)d_in[2];
    const float* b1   = (const float*)d_in[3];
    const float* w2   = (const float*)d_in[4];
    const float* b2   = (const float*)d_in[5];
    const float* wl   = (const float*)d_in[6];
    const float* bl   = (const float*)d_in[7];
    const float* wr   = (const float*)d_in[8];
    float*       out  = (float*)d_out;

    int n  = in_sizes[0] / DIN;   // 100000
    int e  = in_sizes[1] / 2;     // 3200000
    int e8 = e / 8;
    int n4 = (n + 3) / 4;

    k_zero<<<(n4 + 255) / 256, 256>>>(n4);
    k_scatter<<<(e8 + 255) / 256, 256>>>(edge, e8, e);
    k_mlp<<<((size_t)n * 2 + 255) / 256, 256>>>(x, w1, b1, w2, b2, wr, bl, n);

    int warps = (n + NPW - 1) / NPW;
    k_gather<<<((size_t)warps * 32 + 255) / 256, 256>>>(wl, out, n);
}